// round 7
// baseline (speedup 1.0000x reference)
#include <cuda_runtime.h>

// IFOPooling: h_t = f_t * h_{t-1} + i_t * z_t over S (contiguous), per (b,h) row.
// One CTA per row, 128 threads x 16 elements: maximizes per-thread MLP
// (12 back-to-back LDG.128) and minimizes scan-overhead instructions per byte.
// Loads first, single barrier, streaming cache hints (zero-reuse streams).

constexpr int S_LEN  = 2048;
constexpr int NTHR   = 128;
constexpr int PER    = S_LEN / NTHR;   // 16 elements per thread
constexpr int NWARP  = NTHR / 32;      // 4

__global__ __launch_bounds__(NTHR)
void ifo_scan_kernel(const float* __restrict__ f,
                     const float* __restrict__ z,
                     const float* __restrict__ i_,
                     float* __restrict__ out)
{
    const int t    = threadIdx.x;
    const int lane = t & 31;
    const int warp = t >> 5;

    const size_t base = (size_t)blockIdx.x * S_LEN + (size_t)t * PER;

    // ---- 12 independent streaming loads, all issued before any math ----
    float4 f0 = __ldcs(reinterpret_cast<const float4*>(f  + base));
    float4 f1 = __ldcs(reinterpret_cast<const float4*>(f  + base + 4));
    float4 f2 = __ldcs(reinterpret_cast<const float4*>(f  + base + 8));
    float4 f3 = __ldcs(reinterpret_cast<const float4*>(f  + base + 12));
    float4 z0 = __ldcs(reinterpret_cast<const float4*>(z  + base));
    float4 z1 = __ldcs(reinterpret_cast<const float4*>(z  + base + 4));
    float4 z2 = __ldcs(reinterpret_cast<const float4*>(z  + base + 8));
    float4 z3 = __ldcs(reinterpret_cast<const float4*>(z  + base + 12));
    float4 i0 = __ldcs(reinterpret_cast<const float4*>(i_ + base));
    float4 i1 = __ldcs(reinterpret_cast<const float4*>(i_ + base + 4));
    float4 i2 = __ldcs(reinterpret_cast<const float4*>(i_ + base + 8));
    float4 i3 = __ldcs(reinterpret_cast<const float4*>(i_ + base + 12));

    float fv[PER] = {f0.x, f0.y, f0.z, f0.w, f1.x, f1.y, f1.z, f1.w,
                     f2.x, f2.y, f2.z, f2.w, f3.x, f3.y, f3.z, f3.w};
    float xv[PER] = {i0.x * z0.x, i0.y * z0.y, i0.z * z0.z, i0.w * z0.w,
                     i1.x * z1.x, i1.y * z1.y, i1.z * z1.z, i1.w * z1.w,
                     i2.x * z2.x, i2.y * z2.y, i2.z * z2.z, i2.w * z2.w,
                     i3.x * z3.x, i3.y * z3.y, i3.z * z3.z, i3.w * z3.w};

    // ---- Local chunk -> affine pair (A, B): h_out = A*h_in + B ----
    float A = 1.0f, Bc = 0.0f;
    #pragma unroll
    for (int j = 0; j < PER; j++) {
        Bc = fmaf(fv[j], Bc, xv[j]);
        A  = A * fv[j];
    }

    // ---- Intra-warp inclusive scan over pairs ----
    // combine(prev=(Ap,Bp), cur=(Ac,Bc)) = (Ap*Ac, Ac*Bp + Bc)
    float Ai = A, Bi = Bc;
    #pragma unroll
    for (int d = 1; d < 32; d <<= 1) {
        float Au = __shfl_up_sync(0xffffffffu, Ai, d);
        float Bu = __shfl_up_sync(0xffffffffu, Bi, d);
        if (lane >= d) {
            Bi = fmaf(Ai, Bu, Bi);
            Ai = Ai * Au;
        }
    }

    // ---- Cross-warp prefix via shared memory (4 warps, one barrier) ----
    __shared__ float sA[NWARP];
    __shared__ float sB[NWARP];
    if (lane == 31) { sA[warp] = Ai; sB[warp] = Bi; }
    __syncthreads();

    // Exclusive prefix over warps; only the B component matters (h0 = 0).
    float Bw = 0.0f;
    #pragma unroll
    for (int w = 0; w < NWARP; w++) {
        if (w < warp) {
            Bw = fmaf(sA[w], Bw, sB[w]);
        }
    }

    // ---- Thread's exclusive prefix within warp ----
    float Ae = __shfl_up_sync(0xffffffffu, Ai, 1);
    float Be = __shfl_up_sync(0xffffffffu, Bi, 1);
    if (lane == 0) { Ae = 1.0f; Be = 0.0f; }

    // Incoming h for this chunk (h0 = 0): h_in = Ae*Bw + Be
    float h = fmaf(Ae, Bw, Be);

    // ---- Replay chunk from registers, streaming stores ----
    float ov[PER];
    #pragma unroll
    for (int j = 0; j < PER; j++) {
        h = fmaf(fv[j], h, xv[j]);
        ov[j] = h;
    }

    __stcs(reinterpret_cast<float4*>(out + base),
           make_float4(ov[0],  ov[1],  ov[2],  ov[3]));
    __stcs(reinterpret_cast<float4*>(out + base + 4),
           make_float4(ov[4],  ov[5],  ov[6],  ov[7]));
    __stcs(reinterpret_cast<float4*>(out + base + 8),
           make_float4(ov[8],  ov[9],  ov[10], ov[11]));
    __stcs(reinterpret_cast<float4*>(out + base + 12),
           make_float4(ov[12], ov[13], ov[14], ov[15]));
}

extern "C" void kernel_launch(void* const* d_in, const int* in_sizes, int n_in,
                              void* d_out, int out_size)
{
    const float* f = (const float*)d_in[0];
    const float* z = (const float*)d_in[1];
    const float* i = (const float*)d_in[2];
    float* out = (float*)d_out;

    const int n_rows = in_sizes[0] / S_LEN;   // B*H = 16384
    ifo_scan_kernel<<<n_rows, NTHR>>>(f, z, i, out);
}

// round 8
// speedup vs baseline: 1.0437x; 1.0437x over previous
#include <cuda_runtime.h>
#include <cstdint>

// IFOPooling: h_t = f_t * h_{t-1} + i_t * z_t over S (contiguous), per (b,h) row.
// R4 shape (256 threads x 8 elems per row — the measured optimum) with 2 rows
// fused per 512-thread CTA. Each 256-thread half uses its own NAMED barrier and
// private smem, so the halves are fully decoupled; grid halves to 8192 to cut
// dispatch overhead. Streaming cache hints on all zero-reuse streams.

constexpr int S_LEN  = 2048;
constexpr int HALF   = 256;            // threads per row
constexpr int NTHR   = 512;            // 2 rows per CTA
constexpr int PER    = S_LEN / HALF;   // 8 elements per thread
constexpr int NWARP  = HALF / 32;      // 8 warps per row

__global__ __launch_bounds__(NTHR, 4)
void ifo_scan_kernel(const float* __restrict__ f,
                     const float* __restrict__ z,
                     const float* __restrict__ i_,
                     float* __restrict__ out)
{
    const int t    = threadIdx.x;
    const int sub  = t >> 8;           // which row-half (0 or 1)
    const int st   = t & (HALF - 1);   // thread id within the half
    const int lane = t & 31;
    const int warp = (t >> 5) & (NWARP - 1);   // warp id within the half

    const size_t row  = (size_t)blockIdx.x * 2 + sub;
    const size_t base = row * S_LEN + (size_t)st * PER;

    // ---- 6 independent streaming loads, issued before any math ----
    float4 fa = __ldcs(reinterpret_cast<const float4*>(f  + base));
    float4 fb = __ldcs(reinterpret_cast<const float4*>(f  + base + 4));
    float4 za = __ldcs(reinterpret_cast<const float4*>(z  + base));
    float4 zb = __ldcs(reinterpret_cast<const float4*>(z  + base + 4));
    float4 ia = __ldcs(reinterpret_cast<const float4*>(i_ + base));
    float4 ib = __ldcs(reinterpret_cast<const float4*>(i_ + base + 4));

    float fv[PER] = {fa.x, fa.y, fa.z, fa.w, fb.x, fb.y, fb.z, fb.w};
    float xv[PER] = {ia.x * za.x, ia.y * za.y, ia.z * za.z, ia.w * za.w,
                     ib.x * zb.x, ib.y * zb.y, ib.z * zb.z, ib.w * zb.w};

    // ---- Local chunk -> affine pair (A, B): h_out = A*h_in + B ----
    float A = 1.0f, Bc = 0.0f;
    #pragma unroll
    for (int j = 0; j < PER; j++) {
        Bc = fmaf(fv[j], Bc, xv[j]);
        A  = A * fv[j];
    }

    // ---- Intra-warp inclusive scan over pairs ----
    // combine(prev=(Ap,Bp), cur=(Ac,Bc)) = (Ap*Ac, Ac*Bp + Bc)
    float Ai = A, Bi = Bc;
    #pragma unroll
    for (int d = 1; d < 32; d <<= 1) {
        float Au = __shfl_up_sync(0xffffffffu, Ai, d);
        float Bu = __shfl_up_sync(0xffffffffu, Bi, d);
        if (lane >= d) {
            Bi = fmaf(Ai, Bu, Bi);
            Ai = Ai * Au;
        }
    }

    // ---- Cross-warp prefix: per-half smem + per-half NAMED barrier ----
    __shared__ float sA[2][NWARP];
    __shared__ float sB[2][NWARP];
    if (lane == 31) { sA[sub][warp] = Ai; sB[sub][warp] = Bi; }
    // Named barrier: only this half's 256 threads participate.
    asm volatile("bar.sync %0, %1;" :: "r"(sub + 1), "r"(HALF) : "memory");

    // Exclusive prefix over warps; only the B component matters (h0 = 0).
    float Bw = 0.0f;
    #pragma unroll
    for (int w = 0; w < NWARP; w++) {
        if (w < warp) {
            Bw = fmaf(sA[sub][w], Bw, sB[sub][w]);
        }
    }

    // ---- Thread's exclusive prefix within warp ----
    float Ae = __shfl_up_sync(0xffffffffu, Ai, 1);
    float Be = __shfl_up_sync(0xffffffffu, Bi, 1);
    if (lane == 0) { Ae = 1.0f; Be = 0.0f; }

    // Incoming h for this chunk (h0 = 0): h_in = Ae*Bw + Be
    float h = fmaf(Ae, Bw, Be);

    // ---- Replay chunk from registers, streaming stores ----
    float ov[PER];
    #pragma unroll
    for (int j = 0; j < PER; j++) {
        h = fmaf(fv[j], h, xv[j]);
        ov[j] = h;
    }

    __stcs(reinterpret_cast<float4*>(out + base),
           make_float4(ov[0], ov[1], ov[2], ov[3]));
    __stcs(reinterpret_cast<float4*>(out + base + 4),
           make_float4(ov[4], ov[5], ov[6], ov[7]));
}

extern "C" void kernel_launch(void* const* d_in, const int* in_sizes, int n_in,
                              void* d_out, int out_size)
{
    const float* f = (const float*)d_in[0];
    const float* z = (const float*)d_in[1];
    const float* i = (const float*)d_in[2];
    float* out = (float*)d_out;

    const int n_rows = in_sizes[0] / S_LEN;   // B*H = 16384 (even)
    ifo_scan_kernel<<<n_rows / 2, NTHR>>>(f, z, i, out);
}